// round 7
// baseline (speedup 1.0000x reference)
#include <cuda_runtime.h>
#include <cuda_fp16.h>
#include <mma.h>
#include <math.h>

using namespace nvcuda;

#define BB 32
#define CC 64
#define FH 80
#define FW 200
#define HW 16000
#define LANES 64
#define SP 36
#define PE 78
#define J_TOT 2304
#define M_TOT 2048

// ---------------- scratch ----------------
__device__ __half d_featT[BB * HW * CC];          // (B,H,W,C) fp16
__device__ float  d_pool8[BB * 2000 * CC];        // partial pool [b][q][c]
__device__ __half d_xfh[BB * CC * 250];           // pooled context fp16 [b][c][r]
__device__ float  d_weffp[8 * CC * J_TOT];        // fold partials [ck][o][j]
__device__ float  d_beffp[CC * 8];
__device__ __half d_weffh[J_TOT * CC];            // folded weight fp16 [j][o]
__device__ float  d_beff[CC];
__device__ float  d_g[M_TOT * CC];                // attention output [m][c]

__device__ __forceinline__ float warpMaxf(float a) {
#pragma unroll
    for (int off = 16; off > 0; off >>= 1) a = fmaxf(a, __shfl_xor_sync(0xffffffffu, a, off));
    return a;
}
__device__ __forceinline__ float warpSumf(float a) {
#pragma unroll
    for (int off = 16; off > 0; off >>= 1) a += __shfl_xor_sync(0xffffffffu, a, off);
    return a;
}

// ==================== k1: [kA transpose+pool | kC fold] heterogeneous grid =========
// blocks 0..7999: kA (bx = bid%250, b = bid/250). blocks 8000..8511: kC (o,ck).
__global__ void k1_feat_and_fold(const float* __restrict__ feat,
                                 const float* __restrict__ w1,
                                 const float* __restrict__ b1,
                                 const float* __restrict__ fw) {
    __shared__ float tile[64][65];     // kA use (also covers kC's needs below)
    __shared__ float red[256];
    int bid = blockIdx.x;
    int tid = threadIdx.x;

    if (bid < 8000) {
        // ---------- kA: transpose 64c x 64hw tile + pool partials ----------
        int bx = bid % 250, b = bid / 250;
        const float4* src = (const float4*)(feat + (size_t)b * CC * HW + bx * 64);
#pragma unroll
        for (int i = tid; i < 1024; i += 256) {
            int c = i >> 4, x4 = i & 15;
            float4 v = src[(size_t)c * (HW / 4) + x4];
            tile[c][x4 * 4 + 0] = v.x; tile[c][x4 * 4 + 1] = v.y;
            tile[c][x4 * 4 + 2] = v.z; tile[c][x4 * 4 + 3] = v.w;
        }
        __syncthreads();
#pragma unroll
        for (int i = tid; i < 512; i += 256) {
            int row = i >> 3, seg = i & 7;
            __align__(16) __half h[8];
#pragma unroll
            for (int j = 0; j < 8; j++) h[j] = __float2half_rn(tile[seg * 8 + j][row]);
            *(uint4*)(d_featT + ((size_t)b * HW + bx * 64 + row) * CC + seg * 8) = *(uint4*)h;
        }
#pragma unroll
        for (int i = tid; i < 512; i += 256) {
            int q = i >> 6, c = i & 63;
            float s = 0.f;
#pragma unroll
            for (int j = 0; j < 8; j++) s += tile[c][q * 8 + j];
            d_pool8[((size_t)b * 2000 + bx * 8 + q) * CC + c] = s;
        }
    } else {
        // ---------- kC: fold conv1d+fc partials, layout [ck][o][j] ----------
        int idx = bid - 8000;          // 0..511
        int o = idx & 63, ck = idx >> 6;
        int cmBase = ck * 8;
        float* fc_s = &tile[0][0];     // reuse smem (256 floats)
        fc_s[tid] = fw[o * 2048 + cmBase * 32 + tid];
        __syncthreads();
        int cin = tid & 63, s0 = tid >> 6;
        float acc[9];
#pragma unroll
        for (int it = 0; it < 9; it++) acc[it] = 0.f;
#pragma unroll
        for (int cm8 = 0; cm8 < 8; cm8++) {
            int cm = cmBase + cm8;
            float wv[5];
#pragma unroll
            for (int k = 0; k < 5; k++) wv[k] = __ldg(w1 + (cm * CC + cin) * 5 + k);
            const float* frow = fc_s + cm8 * 32;
#pragma unroll
            for (int it = 0; it < 9; it++) {
                int s = s0 + it * 4;
#pragma unroll
                for (int k = 0; k < 5; k++) {
                    int t = s - k;
                    if ((unsigned)t < 32u) acc[it] += frow[t] * wv[k];
                }
            }
        }
#pragma unroll
        for (int it = 0; it < 9; it++)
            d_weffp[(size_t)ck * (CC * J_TOT) + (size_t)o * J_TOT + (tid + it * 256)] = acc[it];
        red[tid] = fc_s[tid] * b1[cmBase + (tid >> 5)];
        __syncthreads();
        for (int st = 128; st > 0; st >>= 1) {
            if (tid < st) red[tid] += red[tid + st];
            __syncthreads();
        }
        if (tid == 0) d_beffp[o * 8 + ck] = red[0];
    }
}

// ==================== k2: [kA2 pool-reduce | kC2 weight-reduce] ====================
// blocks 0..2015: pool reduce (b = bid/63, 4 r's). blocks 2016..2303: kC2.
__global__ void k2_reduce(const float* __restrict__ fb) {
    __shared__ float t_s[64][9];
    int bid = blockIdx.x;
    int tid = threadIdx.x;

    if (bid < 2016) {
        int b = bid / 63, rc = bid % 63;
        int rl = tid >> 6, c = tid & 63;
        int r = rc * 4 + rl;
        if (r < 250) {
            int rh = r / 25, rw = r - rh * 25;
            float acc = 0.f;
#pragma unroll
            for (int dh = 0; dh < 8; dh++)
                acc += d_pool8[((size_t)b * 2000 + (rh * 8 + dh) * 25 + rw) * CC + c];
            d_xfh[((size_t)b * CC + c) * 250 + r] = __float2half_rn(acc * (1.0f / 64.0f));
        }
    } else {
        int idx = bid - 2016;          // 0..287
        int jb = idx % 36, og = idx / 36;
#pragma unroll
        for (int i = tid; i < 512; i += 256) {
            int ol = i >> 6, jl = i & 63;
            float a = 0.f;
#pragma unroll
            for (int ck = 0; ck < 8; ck++)
                a += d_weffp[(size_t)ck * (CC * J_TOT) + (size_t)(og * 8 + ol) * J_TOT + jb * 64 + jl];
            t_s[jl][ol] = a;
        }
        __syncthreads();
        {
            int jl = tid >> 2, op = tid & 3;
            __half2 h = __floats2half2_rn(t_s[jl][2 * op], t_s[jl][2 * op + 1]);
            ((__half2*)d_weffh)[(size_t)(jb * 64 + jl) * 32 + og * 4 + op] = h;
        }
        if (jb == 0 && og == 0 && tid < CC) {
            float s = 0.f;
#pragma unroll
            for (int ck = 0; ck < 8; ck++) s += d_beffp[tid * 8 + ck];
            d_beff[tid] = fb[tid] + s;
        }
    }
}

// ==================== kDE: gather + wmma x_p + attention, fused ====================
// 256 blocks, 256 threads (8 warps). Block = 8 m's = one (b, lane-group).
// dyn smem: rs 36864 (part aliased inside) | xf 32000 = 68864 B -> 3 blocks/SM
__global__ void kDE(const float* __restrict__ prior) {
    extern __shared__ char smraw[];
    __half* rs = (__half*)smraw;                           // 8*2304*2 = 36864 B
    __half2* xf_s = (__half2*)(smraw + 36864);             // 64*125 half2 = 32000 B
    __shared__ int offs0[288], offs1[288], offs2[288], offs3[288];
    __shared__ float xp_s[8 * 64];
    __shared__ float g_buf[8 * 64];

    int m0 = blockIdx.x * 8;
    int b = m0 >> 6;
    int tid = threadIdx.x;
    int w = tid >> 5, lane = tid & 31;

    // full xf slice: 64c x 250r fp16 = 32000 B = 2000 float4 (issued early)
    const float4* xsrc = (const float4*)(d_xfh + (size_t)b * (CC * 250));
#pragma unroll
    for (int i = tid; i < 2000; i += 256) ((float4*)xf_s)[i] = xsrc[i];

    // coordinates -> offsets for 8 m x 36 s
    for (int i = tid; i < 288; i += 256) {
        int ml = i / 36, s = i - ml * 36;
        float px = prior[(size_t)(m0 + ml) * PE + 6 + 2 * s];
        float xs = fminf(px * 0.25f, 199.0f);
        int xc = (int)ceilf(xs), xf_ = (int)floorf(xs);
        double py = 319.0 - (320.0 / 71.0) * (double)(2 * s);
        float ys = fminf((float)py * 0.25f, 79.0f);
        int yc = (int)ceilf(ys), yf_ = (int)floorf(ys);
        offs0[i] = (yc * FW + xc) * CC;
        offs1[i] = (yc * FW + xf_) * CC;
        offs2[i] = (yf_ * FW + xc) * CC;
        offs3[i] = (yf_ * FW + xf_) * CC;
    }
    __syncthreads();

    // gather: warp per point-quad, lane = channel-pair
    const __half2* f2 = (const __half2*)(d_featT + (size_t)b * HW * CC);
    __half2* rs2 = (__half2*)rs;
#pragma unroll 2
    for (int i = w; i < 288; i += 8) {
        int ml = i / 36, s = i - ml * 36;
        float2 v0 = __half22float2(f2[(offs0[i] >> 1) + lane]);
        float2 v1 = __half22float2(f2[(offs1[i] >> 1) + lane]);
        float2 v2 = __half22float2(f2[(offs2[i] >> 1) + lane]);
        float2 v3 = __half22float2(f2[(offs3[i] >> 1) + lane]);
        float2 r;
        r.x = (v0.x + v1.x + v2.x + v3.x) * 0.25f;
        r.y = (v0.y + v1.y + v2.y + v3.y) * 0.25f;
        rs2[((ml * J_TOT + s * CC) >> 1) + lane] = __float22half2_rn(r);
    }
    __syncthreads();

    // wmma m8n32k16: warp w -> otile = w>>2 (32 o's), kq = w&3 (36 ksteps)
    float* part = (float*)rs;   // aliased AFTER all rs reads complete (sync below)
    {
        int otile = w >> 2, kq = w & 3;
        wmma::fragment<wmma::matrix_a, 8, 32, 16, __half, wmma::row_major> af;
        wmma::fragment<wmma::matrix_b, 8, 32, 16, __half, wmma::row_major> bf;
        wmma::fragment<wmma::accumulator, 8, 32, 16, float> cf;
        wmma::fill_fragment(cf, 0.0f);
        for (int ks = kq * 36; ks < kq * 36 + 36; ks++) {
            int k0 = ks * 16;
            wmma::load_matrix_sync(af, rs + k0, J_TOT);
            wmma::load_matrix_sync(bf, d_weffh + (size_t)k0 * CC + otile * 32, CC);
            wmma::mma_sync(cf, af, bf, cf);
        }
        __syncthreads();   // all warps done READING rs; accum lives in registers
        wmma::store_matrix_sync(part + w * 256, cf, 32, wmma::mem_row_major);
    }
    __syncthreads();

    // combine k-quarters + bias -> xp_s[m][o]
    for (int i = tid; i < 512; i += 256) {
        int m = i >> 6, o = i & 63;
        int ot = o >> 5, ol = o & 31;
        float v = part[(ot * 4 + 0) * 256 + m * 32 + ol]
                + part[(ot * 4 + 1) * 256 + m * 32 + ol]
                + part[(ot * 4 + 2) * 256 + m * 32 + ol]
                + part[(ot * 4 + 3) * 256 + m * 32 + ol] + d_beff[o];
        xp_s[i] = v;
    }
    __syncthreads();

    // attention: warp w handles m = m0 + w
    const float* xpw = xp_s + w * 64;
    int pr[4]; bool ok[4];
#pragma unroll
    for (int k = 0; k < 4; k++) {
        int p = lane + 32 * k;
        ok[k] = p < 125;
        pr[k] = ok[k] ? p : 124;
    }
    float sx[4] = {0, 0, 0, 0}, sy[4] = {0, 0, 0, 0};
    for (int c = 0; c < 64; c++) {
        float xc = xpw[c];
        const __half2* row = xf_s + c * 125;
#pragma unroll
        for (int k = 0; k < 4; k++) {
            float2 v = __half22float2(row[pr[k]]);
            sx[k] += xc * v.x;
            sy[k] += xc * v.y;
        }
    }
    float mx = -INFINITY;
#pragma unroll
    for (int k = 0; k < 4; k++) {
        sx[k] = ok[k] ? sx[k] * 0.125f : -INFINITY;
        sy[k] = ok[k] ? sy[k] * 0.125f : -INFINITY;
        mx = fmaxf(mx, fmaxf(sx[k], sy[k]));
    }
    mx = warpMaxf(mx);
    float wx[4], wy[4], wsum = 0.f;
#pragma unroll
    for (int k = 0; k < 4; k++) {
        wx[k] = ok[k] ? expf(sx[k] - mx) : 0.f;
        wy[k] = ok[k] ? expf(sy[k] - mx) : 0.f;
        wsum += wx[k] + wy[k];
    }
    wsum = warpSumf(wsum);
    float inv = 1.0f / wsum;
#pragma unroll
    for (int k = 0; k < 4; k++) { wx[k] *= inv; wy[k] *= inv; }

    for (int c = 0; c < 64; c++) {
        const __half2* row = xf_s + c * 125;
        float a = 0.f;
#pragma unroll
        for (int k = 0; k < 4; k++) {
            float2 v = __half22float2(row[pr[k]]);
            a += wx[k] * v.x + wy[k] * v.y;
        }
        a = warpSumf(a);
        if (lane == 0) g_buf[w * 64 + c] = a;
    }
    __syncthreads();
    for (int i = tid; i < 512; i += 256) {
        int ml = i >> 6, c = i & 63;
        d_g[(size_t)(m0 + ml) * CC + c] = g_buf[i];
    }
}

// ==================== kE3: conv1x1 + relu + residual, per (b, o-group) =============
__global__ void kE3_out(const float* __restrict__ w1x1, const float* __restrict__ b1x1,
                        const float* __restrict__ prior, float* __restrict__ out) {
    __shared__ float g_s[4096];
    __shared__ float gr_s[8];
    int b = blockIdx.x, og = blockIdx.y;
    int tid = threadIdx.x, w = tid >> 5, lid = tid & 31;
    const float4* gsrc = (const float4*)(d_g + (size_t)b * 4096);
    for (int i = tid; i < 1024; i += 256) ((float4*)g_s)[i] = gsrc[i];
    __syncthreads();
    int o = og * 8 + w;
    const float4* wr = (const float4*)(w1x1 + (size_t)o * 4096);
    float a = 0.f;
#pragma unroll 4
    for (int j4 = lid; j4 < 1024; j4 += 32) {
        float4 wv = wr[j4];
        float4 gv = ((const float4*)g_s)[j4];
        a += wv.x * gv.x + wv.y * gv.y + wv.z * gv.z + wv.w * gv.w;
    }
    a = warpSumf(a);
    if (lid == 0) gr_s[w] = fmaxf(a + b1x1[o], 0.f);
    __syncthreads();
    for (int e = tid; e < 8 * PE; e += 256) {
        int jl = e / PE, t = e - jl * PE;
        size_t idx = (size_t)b * (64 * PE) + (size_t)(og * 8 + jl) * PE + t;
        out[idx] = gr_s[jl] + prior[idx];
    }
}

// ---------------- host launcher ----------------------------------------------------
extern "C" void kernel_launch(void* const* d_in, const int* in_sizes, int n_in,
                              void* d_out, int out_size) {
    const float* feature = (const float*)d_in[0];
    const float* prior   = (const float*)d_in[1];
    const float* w1      = (const float*)d_in[2];
    const float* b1      = (const float*)d_in[3];
    const float* fw      = (const float*)d_in[4];
    const float* fb      = (const float*)d_in[5];
    const float* w1x1    = (const float*)d_in[6];
    const float* b1x1    = (const float*)d_in[7];
    float* out = (float*)d_out;

    const int kde_smem = 36864 + 32000;   // rs(+part alias) | xf = 68864 B
    cudaFuncSetAttribute(kDE, cudaFuncAttributeMaxDynamicSharedMemorySize, kde_smem);

    k1_feat_and_fold<<<8512, 256>>>(feature, w1, b1, fw);
    k2_reduce<<<2304, 256>>>(fb);
    kDE<<<M_TOT / 8, 256, kde_smem>>>(prior);
    kE3_out<<<dim3(BB, 8), 256>>>(w1x1, b1x1, prior, out);
}

// round 8
// speedup vs baseline: 1.0936x; 1.0936x over previous
#include <cuda_runtime.h>
#include <cuda_fp16.h>
#include <mma.h>
#include <math.h>

using namespace nvcuda;

#define BB 32
#define CC 64
#define FH 80
#define FW 200
#define HW 16000
#define LANES 64
#define SP 36
#define PE 78
#define J_TOT 2304
#define M_TOT 2048

// ---------------- scratch ----------------
__device__ __half d_featT[BB * HW * CC];          // (B,H,W,C) fp16
__device__ float  d_pool8[BB * 2000 * CC];        // partial pool [b][q][c]
__device__ __half d_xfh[BB * CC * 250];           // pooled context fp16 [b][c][r]
__device__ float  d_weffp[8 * CC * J_TOT];        // fold partials [ck][o][j]
__device__ float  d_beffp[CC * 8];
__device__ __half d_weffh[J_TOT * CC];            // folded weight fp16 [j][o]
__device__ float  d_beff[CC];
__device__ float  d_g[M_TOT * CC];                // attention output [m][c]

__device__ __forceinline__ float warpMaxf(float a) {
#pragma unroll
    for (int off = 16; off > 0; off >>= 1) a = fmaxf(a, __shfl_xor_sync(0xffffffffu, a, off));
    return a;
}
__device__ __forceinline__ float warpSumf(float a) {
#pragma unroll
    for (int off = 16; off > 0; off >>= 1) a += __shfl_xor_sync(0xffffffffu, a, off);
    return a;
}

// ==================== k1: [kC fold | kA transpose+pool] heterogeneous grid =========
// blocks 0..511: kC (run in wave 1, hide under kA). blocks 512..8511: kA.
__global__ void k1_feat_and_fold(const float* __restrict__ feat,
                                 const float* __restrict__ w1,
                                 const float* __restrict__ b1,
                                 const float* __restrict__ fw) {
    __shared__ float tile[64][65];
    __shared__ float red[256];
    int bid = blockIdx.x;
    int tid = threadIdx.x;

    if (bid >= 512) {
        // ---------- kA: transpose 64c x 64hw tile + pool partials ----------
        int ab = bid - 512;
        int bx = ab % 250, b = ab / 250;
        const float4* src = (const float4*)(feat + (size_t)b * CC * HW + bx * 64);
#pragma unroll
        for (int i = tid; i < 1024; i += 256) {
            int c = i >> 4, x4 = i & 15;
            float4 v = src[(size_t)c * (HW / 4) + x4];
            tile[c][x4 * 4 + 0] = v.x; tile[c][x4 * 4 + 1] = v.y;
            tile[c][x4 * 4 + 2] = v.z; tile[c][x4 * 4 + 3] = v.w;
        }
        __syncthreads();
#pragma unroll
        for (int i = tid; i < 512; i += 256) {
            int row = i >> 3, seg = i & 7;
            __align__(16) __half h[8];
#pragma unroll
            for (int j = 0; j < 8; j++) h[j] = __float2half_rn(tile[seg * 8 + j][row]);
            *(uint4*)(d_featT + ((size_t)b * HW + bx * 64 + row) * CC + seg * 8) = *(uint4*)h;
        }
#pragma unroll
        for (int i = tid; i < 512; i += 256) {
            int q = i >> 6, c = i & 63;
            float s = 0.f;
#pragma unroll
            for (int j = 0; j < 8; j++) s += tile[c][q * 8 + j];
            d_pool8[((size_t)b * 2000 + bx * 8 + q) * CC + c] = s;
        }
    } else {
        // ---------- kC: fold conv1d+fc partials, layout [ck][o][j] ----------
        int o = bid & 63, ck = bid >> 6;
        int cmBase = ck * 8;
        float* fc_s = &tile[0][0];
        fc_s[tid] = fw[o * 2048 + cmBase * 32 + tid];
        __syncthreads();
        int cin = tid & 63, s0 = tid >> 6;
        float acc[9];
#pragma unroll
        for (int it = 0; it < 9; it++) acc[it] = 0.f;
#pragma unroll
        for (int cm8 = 0; cm8 < 8; cm8++) {
            int cm = cmBase + cm8;
            float wv[5];
#pragma unroll
            for (int k = 0; k < 5; k++) wv[k] = __ldg(w1 + (cm * CC + cin) * 5 + k);
            const float* frow = fc_s + cm8 * 32;
#pragma unroll
            for (int it = 0; it < 9; it++) {
                int s = s0 + it * 4;
#pragma unroll
                for (int k = 0; k < 5; k++) {
                    int t = s - k;
                    if ((unsigned)t < 32u) acc[it] += frow[t] * wv[k];
                }
            }
        }
#pragma unroll
        for (int it = 0; it < 9; it++)
            d_weffp[(size_t)ck * (CC * J_TOT) + (size_t)o * J_TOT + (tid + it * 256)] = acc[it];
        red[tid] = fc_s[tid] * b1[cmBase + (tid >> 5)];
        __syncthreads();
        for (int st = 128; st > 0; st >>= 1) {
            if (tid < st) red[tid] += red[tid + st];
            __syncthreads();
        }
        if (tid == 0) d_beffp[o * 8 + ck] = red[0];
    }
}

// ==================== k2: [kC2 weight-reduce | kA2 pool-reduce] ====================
// blocks 0..287: kC2 (first wave). blocks 288..2303: pool reduce (4 r's each).
__global__ void k2_reduce(const float* __restrict__ fb) {
    __shared__ float t_s[64][9];
    int bid = blockIdx.x;
    int tid = threadIdx.x;

    if (bid >= 288) {
        int pb = bid - 288;
        int b = pb / 63, rc = pb % 63;
        int rl = tid >> 6, c = tid & 63;
        int r = rc * 4 + rl;
        if (r < 250) {
            int rh = r / 25, rw = r - rh * 25;
            float acc = 0.f;
#pragma unroll
            for (int dh = 0; dh < 8; dh++)
                acc += d_pool8[((size_t)b * 2000 + (rh * 8 + dh) * 25 + rw) * CC + c];
            d_xfh[((size_t)b * CC + c) * 250 + r] = __float2half_rn(acc * (1.0f / 64.0f));
        }
    } else {
        int jb = bid % 36, og = bid / 36;
#pragma unroll
        for (int i = tid; i < 512; i += 256) {
            int ol = i >> 6, jl = i & 63;
            float a = 0.f;
#pragma unroll
            for (int ck = 0; ck < 8; ck++)
                a += d_weffp[(size_t)ck * (CC * J_TOT) + (size_t)(og * 8 + ol) * J_TOT + jb * 64 + jl];
            t_s[jl][ol] = a;
        }
        __syncthreads();
        {
            int jl = tid >> 2, op = tid & 3;
            __half2 h = __floats2half2_rn(t_s[jl][2 * op], t_s[jl][2 * op + 1]);
            ((__half2*)d_weffh)[(size_t)(jb * 64 + jl) * 32 + og * 4 + op] = h;
        }
        if (jb == 0 && og == 0 && tid < CC) {
            float s = 0.f;
#pragma unroll
            for (int ck = 0; ck < 8; ck++) s += d_beffp[tid * 8 + ck];
            d_beff[tid] = fb[tid] + s;
        }
    }
}

// ==================== kDE: gather + wmma x_p + attention, fused ====================
// 256 blocks, 256 threads (8 warps). Block = 8 m's = one (b, lane-group).
// dyn smem: rs 36864 (part aliased inside) | xf 32000 = 68864 B -> 3 blocks/SM
__global__ void kDE(const float* __restrict__ prior) {
    extern __shared__ char smraw[];
    __half* rs = (__half*)smraw;                           // 8*2304*2 = 36864 B
    __half2* xf_s = (__half2*)(smraw + 36864);             // 64*125 half2 = 32000 B
    __shared__ int offs0[288], offs1[288], offs2[288], offs3[288];
    __shared__ float xp_s[8 * 64];
    __shared__ float g_buf[8 * 64];

    int m0 = blockIdx.x * 8;
    int b = m0 >> 6;
    int tid = threadIdx.x;
    int w = tid >> 5, lane = tid & 31;

    // full xf slice: 64c x 250r fp16 = 32000 B = 2000 float4 (issued early)
    const float4* xsrc = (const float4*)(d_xfh + (size_t)b * (CC * 250));
#pragma unroll
    for (int i = tid; i < 2000; i += 256) ((float4*)xf_s)[i] = xsrc[i];

    // coordinates -> offsets for 8 m x 36 s
    for (int i = tid; i < 288; i += 256) {
        int ml = i / 36, s = i - ml * 36;
        float px = prior[(size_t)(m0 + ml) * PE + 6 + 2 * s];
        float xs = fminf(px * 0.25f, 199.0f);
        int xc = (int)ceilf(xs), xf_ = (int)floorf(xs);
        double py = 319.0 - (320.0 / 71.0) * (double)(2 * s);
        float ys = fminf((float)py * 0.25f, 79.0f);
        int yc = (int)ceilf(ys), yf_ = (int)floorf(ys);
        offs0[i] = (yc * FW + xc) * CC;
        offs1[i] = (yc * FW + xf_) * CC;
        offs2[i] = (yf_ * FW + xc) * CC;
        offs3[i] = (yf_ * FW + xf_) * CC;
    }
    __syncthreads();

    // gather: warp per point-quad, lane = channel-pair
    const __half2* f2 = (const __half2*)(d_featT + (size_t)b * HW * CC);
    __half2* rs2 = (__half2*)rs;
#pragma unroll 2
    for (int i = w; i < 288; i += 8) {
        int ml = i / 36, s = i - ml * 36;
        float2 v0 = __half22float2(f2[(offs0[i] >> 1) + lane]);
        float2 v1 = __half22float2(f2[(offs1[i] >> 1) + lane]);
        float2 v2 = __half22float2(f2[(offs2[i] >> 1) + lane]);
        float2 v3 = __half22float2(f2[(offs3[i] >> 1) + lane]);
        float2 r;
        r.x = (v0.x + v1.x + v2.x + v3.x) * 0.25f;
        r.y = (v0.y + v1.y + v2.y + v3.y) * 0.25f;
        rs2[((ml * J_TOT + s * CC) >> 1) + lane] = __float22half2_rn(r);
    }
    __syncthreads();

    // wmma m8n32k16: warp w -> otile = w>>2 (32 o's), kq = w&3 (36 ksteps)
    float* part = (float*)rs;   // aliased AFTER all rs reads complete (sync below)
    {
        int otile = w >> 2, kq = w & 3;
        wmma::fragment<wmma::matrix_a, 8, 32, 16, __half, wmma::row_major> af;
        wmma::fragment<wmma::matrix_b, 8, 32, 16, __half, wmma::row_major> bf;
        wmma::fragment<wmma::accumulator, 8, 32, 16, float> cf;
        wmma::fill_fragment(cf, 0.0f);
        for (int ks = kq * 36; ks < kq * 36 + 36; ks++) {
            int k0 = ks * 16;
            wmma::load_matrix_sync(af, rs + k0, J_TOT);
            wmma::load_matrix_sync(bf, d_weffh + (size_t)k0 * CC + otile * 32, CC);
            wmma::mma_sync(cf, af, bf, cf);
        }
        __syncthreads();   // all warps done READING rs; accum lives in registers
        wmma::store_matrix_sync(part + w * 256, cf, 32, wmma::mem_row_major);
    }
    __syncthreads();

    // combine k-quarters + bias -> xp_s[m][o]
    for (int i = tid; i < 512; i += 256) {
        int m = i >> 6, o = i & 63;
        int ot = o >> 5, ol = o & 31;
        float v = part[(ot * 4 + 0) * 256 + m * 32 + ol]
                + part[(ot * 4 + 1) * 256 + m * 32 + ol]
                + part[(ot * 4 + 2) * 256 + m * 32 + ol]
                + part[(ot * 4 + 3) * 256 + m * 32 + ol] + d_beff[o];
        xp_s[i] = v;
    }
    __syncthreads();

    // attention: warp w handles m = m0 + w
    const float* xpw = xp_s + w * 64;
    int pr[4]; bool ok[4];
#pragma unroll
    for (int k = 0; k < 4; k++) {
        int p = lane + 32 * k;
        ok[k] = p < 125;
        pr[k] = ok[k] ? p : 124;
    }
    float sx[4] = {0, 0, 0, 0}, sy[4] = {0, 0, 0, 0};
    for (int c = 0; c < 64; c++) {
        float xc = xpw[c];
        const __half2* row = xf_s + c * 125;
#pragma unroll
        for (int k = 0; k < 4; k++) {
            float2 v = __half22float2(row[pr[k]]);
            sx[k] += xc * v.x;
            sy[k] += xc * v.y;
        }
    }
    float mx = -INFINITY;
#pragma unroll
    for (int k = 0; k < 4; k++) {
        sx[k] = ok[k] ? sx[k] * 0.125f : -INFINITY;
        sy[k] = ok[k] ? sy[k] * 0.125f : -INFINITY;
        mx = fmaxf(mx, fmaxf(sx[k], sy[k]));
    }
    mx = warpMaxf(mx);
    float wx[4], wy[4], wsum = 0.f;
#pragma unroll
    for (int k = 0; k < 4; k++) {
        wx[k] = ok[k] ? expf(sx[k] - mx) : 0.f;
        wy[k] = ok[k] ? expf(sy[k] - mx) : 0.f;
        wsum += wx[k] + wy[k];
    }
    wsum = warpSumf(wsum);
    float inv = 1.0f / wsum;
#pragma unroll
    for (int k = 0; k < 4; k++) { wx[k] *= inv; wy[k] *= inv; }

    for (int c = 0; c < 64; c++) {
        const __half2* row = xf_s + c * 125;
        float a = 0.f;
#pragma unroll
        for (int k = 0; k < 4; k++) {
            float2 v = __half22float2(row[pr[k]]);
            a += wx[k] * v.x + wy[k] * v.y;
        }
        a = warpSumf(a);
        if (lane == 0) g_buf[w * 64 + c] = a;
    }
    __syncthreads();
    for (int i = tid; i < 512; i += 256) {
        int ml = i >> 6, c = i & 63;
        d_g[(size_t)(m0 + ml) * CC + c] = g_buf[i];
    }
}

// ==================== kE3: conv1x1 + relu + residual ===============================
// grid (32, 8), 512 threads: 16 warps = 8 o's x 2 K-halves.
__global__ void kE3_out(const float* __restrict__ w1x1, const float* __restrict__ b1x1,
                        const float* __restrict__ prior, float* __restrict__ out) {
    __shared__ float g_s[4096];
    __shared__ float part_s[16];
    __shared__ float gr_s[8];
    int b = blockIdx.x, og = blockIdx.y;
    int tid = threadIdx.x, w = tid >> 5, lid = tid & 31;
    const float4* gsrc = (const float4*)(d_g + (size_t)b * 4096);
#pragma unroll
    for (int i = tid; i < 1024; i += 512) ((float4*)g_s)[i] = gsrc[i];
    __syncthreads();
    int ol = w >> 1, kh = w & 1;
    int o = og * 8 + ol;
    const float4* wr = (const float4*)(w1x1 + (size_t)o * 4096) + kh * 512;
    const float4* gs4 = ((const float4*)g_s) + kh * 512;
    float a = 0.f;
#pragma unroll 4
    for (int j4 = lid; j4 < 512; j4 += 32) {
        float4 wv = wr[j4];
        float4 gv = gs4[j4];
        a += wv.x * gv.x + wv.y * gv.y + wv.z * gv.z + wv.w * gv.w;
    }
    a = warpSumf(a);
    if (lid == 0) part_s[w] = a;
    __syncthreads();
    if (tid < 8)
        gr_s[tid] = fmaxf(part_s[2 * tid] + part_s[2 * tid + 1] + b1x1[og * 8 + tid], 0.f);
    __syncthreads();
    for (int e = tid; e < 8 * PE; e += 512) {
        int jl = e / PE, t = e - jl * PE;
        size_t idx = (size_t)b * (64 * PE) + (size_t)(og * 8 + jl) * PE + t;
        out[idx] = gr_s[jl] + prior[idx];
    }
}

// ---------------- host launcher ----------------------------------------------------
extern "C" void kernel_launch(void* const* d_in, const int* in_sizes, int n_in,
                              void* d_out, int out_size) {
    const float* feature = (const float*)d_in[0];
    const float* prior   = (const float*)d_in[1];
    const float* w1      = (const float*)d_in[2];
    const float* b1      = (const float*)d_in[3];
    const float* fw      = (const float*)d_in[4];
    const float* fb      = (const float*)d_in[5];
    const float* w1x1    = (const float*)d_in[6];
    const float* b1x1    = (const float*)d_in[7];
    float* out = (float*)d_out;

    const int kde_smem = 36864 + 32000;   // rs(+part alias) | xf = 68864 B
    cudaFuncSetAttribute(kDE, cudaFuncAttributeMaxDynamicSharedMemorySize, kde_smem);

    k1_feat_and_fold<<<8512, 256>>>(feature, w1, b1, fw);
    k2_reduce<<<2304, 256>>>(fb);
    kDE<<<M_TOT / 8, 256, kde_smem>>>(prior);
    kE3_out<<<dim3(BB, 8), 512>>>(w1x1, b1x1, prior, out);
}